// round 12
// baseline (speedup 1.0000x reference)
#include <cuda_runtime.h>
#include <cuda_bf16.h>

#define N_TOK 8192
#define C_IN  256
#define C2    128
#define HWX   1024
#define BATCH 8
#define KTOT  262144
#define DSLICES 256
#define DROWS   1024

// ---------------- scratch (device globals per harness rules) ----------------
__device__ __align__(16) __nv_bfloat16 g_xbf[N_TOK*C_IN];
__device__ __align__(16) __nv_bfloat16 g_Wbf[3*C_IN*C2];
__device__ __align__(16) __nv_bfloat16 g_theta[N_TOK*C2];
__device__ __align__(16) __nv_bfloat16 g_phi[N_TOK*C2];
__device__ __align__(16) __nv_bfloat16 g_alpha[N_TOK*C2];
__device__ __align__(16) float g_oattn[N_TOK*C2];
__device__ __align__(16) float g_partial[DSLICES*BATCH*HWX];
__device__ __align__(16) float g_logits[BATCH*HWX];
__device__ __align__(16) float g_sp[BATCH*HWX];
// flash split-K partials (2 halves)
__device__ __align__(16) float g_fO[2*N_TOK*C2];
__device__ __align__(16) float g_fm[2*N_TOK];
__device__ __align__(16) float g_fl[2*N_TOK];

// ---------------- helpers ----------------
__device__ __forceinline__ unsigned smem_u32(const void* p){
  return (unsigned)__cvta_generic_to_shared(p);
}
__device__ __forceinline__ void ldmatrix_x4(unsigned &r0, unsigned &r1, unsigned &r2, unsigned &r3, unsigned addr){
  asm volatile("ldmatrix.sync.aligned.m8n8.x4.shared.b16 {%0,%1,%2,%3}, [%4];"
    : "=r"(r0),"=r"(r1),"=r"(r2),"=r"(r3) : "r"(addr));
}
__device__ __forceinline__ void ldmatrix_x4_trans(unsigned &r0, unsigned &r1, unsigned &r2, unsigned &r3, unsigned addr){
  asm volatile("ldmatrix.sync.aligned.m8n8.x4.trans.shared.b16 {%0,%1,%2,%3}, [%4];"
    : "=r"(r0),"=r"(r1),"=r"(r2),"=r"(r3) : "r"(addr));
}
__device__ __forceinline__ void mma_bf16(float* d, const unsigned* a, unsigned b0, unsigned b1){
  asm volatile("mma.sync.aligned.m16n8k16.row.col.f32.bf16.bf16.f32 "
    "{%0,%1,%2,%3}, {%4,%5,%6,%7}, {%8,%9}, {%0,%1,%2,%3};"
    : "+f"(d[0]),"+f"(d[1]),"+f"(d[2]),"+f"(d[3])
    : "r"(a[0]),"r"(a[1]),"r"(a[2]),"r"(a[3]),"r"(b0),"r"(b1));
}
__device__ __forceinline__ float ex2f_(float x){ float y; asm("ex2.approx.ftz.f32 %0, %1;" : "=f"(y) : "f"(x)); return y; }
__device__ __forceinline__ unsigned pack_bf2(float lo, float hi){
  unsigned u; asm("cvt.rn.bf16x2.f32 %0, %1, %2;" : "=r"(u) : "f"(hi), "f"(lo)); return u;
}
__device__ __forceinline__ void cp_async16(void* sdst, const void* gsrc){
  asm volatile("cp.async.cg.shared.global [%0], [%1], 16;"
    :: "r"(smem_u32(sdst)), "l"(gsrc));
}
#define CP_COMMIT() asm volatile("cp.async.commit_group;" ::: "memory")
#define CP_WAIT(N)  asm volatile("cp.async.wait_group %0;" :: "n"(N) : "memory")
#define GBAR(id)    asm volatile("bar.sync %0, 128;" :: "r"(id) : "memory")
#define LOG2E 1.4426950408889634f

// ============================================================================
// Kernel 0: one-time bf16 conversion of x and the three projection weights.
// ============================================================================
__global__ __launch_bounds__(256) void convert_kernel(
    const float* __restrict__ x,
    const float* __restrict__ Wt, const float* __restrict__ Wp, const float* __restrict__ Wa)
{
  int t = threadIdx.x;
  if(blockIdx.x < 512){
    const float4* x4 = (const float4*)x;
    #pragma unroll
    for(int k=0;k<4;k++){
      size_t i = (size_t)blockIdx.x*1024 + k*256 + t;   // < 524288
      float4 v = x4[i];
      __nv_bfloat162 a = __float22bfloat162_rn(make_float2(v.x,v.y));
      __nv_bfloat162 b = __float22bfloat162_rn(make_float2(v.z,v.w));
      *(__nv_bfloat162*)(g_xbf + i*4    ) = a;
      *(__nv_bfloat162*)(g_xbf + i*4 + 2) = b;
    }
  } else {
    int idx = (blockIdx.x-512)*256 + t;                 // 0..16383
    for(; idx < 24576; idx += 64*256){
      int which = idx >> 13, off = idx & 8191;
      const float4* src = (const float4*)(which==0?Wt:(which==1?Wp:Wa));
      float4 v = src[off];
      __nv_bfloat162 a = __float22bfloat162_rn(make_float2(v.x,v.y));
      __nv_bfloat162 b = __float22bfloat162_rn(make_float2(v.z,v.w));
      __nv_bfloat16* dst = g_Wbf + which*C_IN*C2 + off*4;
      *(__nv_bfloat162*)(dst  ) = a;
      *(__nv_bfloat162*)(dst+2) = b;
    }
  }
}

// ============================================================================
// Kernel 1: projections theta/phi/alpha = x @ W + b  (bf16 mma, cp.async tiles)
// ============================================================================
#define PROJ_SMEM ((64*264 + 256*136)*2)
__global__ __launch_bounds__(128) void proj_kernel(
    const float* __restrict__ bt, const float* __restrict__ bp, const float* __restrict__ ba)
{
  extern __shared__ __nv_bfloat16 smem[];
  __nv_bfloat16* sA = smem;            // [64][264]
  __nv_bfloat16* sB = smem + 64*264;   // [256][136]
  const float* bias; __nv_bfloat16* outp;
  if      (blockIdx.z==0){bias=bt;outp=g_theta;}
  else if (blockIdx.z==1){bias=bp;outp=g_phi;}
  else                   {bias=ba;outp=g_alpha;}
  const __nv_bfloat16* W = g_Wbf + blockIdx.z*C_IN*C2;
  int t=threadIdx.x, lane=t&31, warp=t>>5;
  int m0 = blockIdx.x*64;

  for(int idx=t; idx<2048; idx+=128){
    int r=idx>>5, c=idx&31;
    cp_async16(sA + r*264 + c*8, g_xbf + (size_t)(m0+r)*C_IN + c*8);
  }
  for(int idx=t; idx<4096; idx+=128){
    int r=idx>>4, c=idx&15;
    cp_async16(sB + r*136 + c*8, W + r*C2 + c*8);
  }
  CP_COMMIT(); CP_WAIT(0);
  __syncthreads();

  float acc[16][4];
  #pragma unroll
  for(int i=0;i<16;i++){acc[i][0]=acc[i][1]=acc[i][2]=acc[i][3]=0.f;}
  int lr16 = lane&15, lh8 = (lane>>4)*8;

  #pragma unroll
  for(int kk=0;kk<16;kk++){
    unsigned af[4];
    ldmatrix_x4(af[0],af[1],af[2],af[3], smem_u32(sA + (warp*16+lr16)*264 + kk*16 + lh8));
    #pragma unroll
    for(int n2=0;n2<8;n2++){
      unsigned r0,r1,r2,r3;
      ldmatrix_x4_trans(r0,r1,r2,r3, smem_u32(sB + (kk*16+lr16)*136 + n2*16 + lh8));
      mma_bf16(acc[2*n2  ], af, r0, r1);
      mma_bf16(acc[2*n2+1], af, r2, r3);
    }
  }
  int row = m0 + warp*16 + (lane>>2);
  #pragma unroll
  for(int nt=0;nt<16;nt++){
    int col = nt*8 + (lane&3)*2;
    float b0v = bias[col], b1v = bias[col+1];
    *(__nv_bfloat162*)(outp + (size_t)row*C2 + col)
        = __float22bfloat162_rn(make_float2(acc[nt][0]+b0v, acc[nt][1]+b1v));
    *(__nv_bfloat162*)(outp + (size_t)(row+8)*C2 + col)
        = __float22bfloat162_rn(make_float2(acc[nt][2]+b0v, acc[nt][3]+b1v));
  }
}

// ============================================================================
// Kernel 2: dense gate split-K partials (proven config: grid 256 x 1024 rows)
// ============================================================================
__global__ __launch_bounds__(256) void dense_partial_kernel(
    const float* __restrict__ x, const float* __restrict__ Wd)
{
  __shared__ float xs[8*DROWS];
  int t = threadIdx.x;
  int i0 = blockIdx.x*DROWS;
  for(int idx=t; idx<2048; idx+=256){
    int b=idx>>8, c4=idx&255;
    *(float4*)&xs[b*DROWS + c4*4] = *(const float4*)&x[(size_t)b*KTOT + i0 + c4*4];
  }
  __syncthreads();
  unsigned long long acc0[8], acc1[8];
  #pragma unroll
  for(int b=0;b<8;b++){acc0[b]=0ull; acc1[b]=0ull;}
  const float4* W4 = (const float4*)Wd + (size_t)i0*256 + t;
  #pragma unroll 8
  for(int i=0;i<DROWS;i++){
    float4 w = __ldcs(&W4[(size_t)i*256]);
    unsigned long long w01, w23;
    asm("mov.b64 %0, {%1,%2};" : "=l"(w01) : "f"(w.x), "f"(w.y));
    asm("mov.b64 %0, {%1,%2};" : "=l"(w23) : "f"(w.z), "f"(w.w));
    #pragma unroll
    for(int b=0;b<8;b++){
      float xv = xs[b*DROWS+i];
      unsigned long long xx;
      asm("mov.b64 %0, {%1,%1};" : "=l"(xx) : "f"(xv));
      asm("fma.rn.f32x2 %0, %1, %2, %0;" : "+l"(acc0[b]) : "l"(w01), "l"(xx));
      asm("fma.rn.f32x2 %0, %1, %2, %0;" : "+l"(acc1[b]) : "l"(w23), "l"(xx));
    }
  }
  float* out = g_partial + (size_t)blockIdx.x*8192;
  #pragma unroll
  for(int b=0;b<8;b++){
    float lo0,hi0,lo1,hi1;
    asm("mov.b64 {%0,%1}, %2;" : "=f"(lo0),"=f"(hi0) : "l"(acc0[b]));
    asm("mov.b64 {%0,%1}, %2;" : "=f"(lo1),"=f"(hi1) : "l"(acc1[b]));
    *(float4*)&out[b*1024 + t*4] = make_float4(lo0,hi0,lo1,hi1);
  }
}

// ============================================================================
// Kernel 3a: reduce DSLICES partial slices -> g_logits[8192].
// ============================================================================
__global__ __launch_bounds__(256) void reduce_kernel(){
  __shared__ float red[256];
  int t = threadIdx.x;
  int c = t & 31, r = t >> 5;
  int col = blockIdx.x*32 + c;
  float s = 0.f;
  #pragma unroll 8
  for(int sl=r; sl<DSLICES; sl+=8) s += g_partial[(size_t)sl*8192 + col];
  red[t] = s;
  __syncthreads();
  if(t<128) red[t] += red[t+128];
  __syncthreads();
  if(t<64)  red[t] += red[t+64];
  __syncthreads();
  if(t<32)  g_logits[blockIdx.x*32 + t] = red[t] + red[t+32];
}

// ============================================================================
// Kernel 3b: softmax over 1024 positions per batch.
// ============================================================================
__global__ __launch_bounds__(256) void sp_softmax_kernel(const float* __restrict__ bd){
  int b = blockIdx.x, t = threadIdx.x, lane = t&31, warp = t>>5;
  __shared__ float sred[8];
  float v[4];
  #pragma unroll
  for(int jj=0;jj<4;jj++) v[jj] = g_logits[b*1024 + t + jj*256] + bd[t + jj*256];
  float mx = fmaxf(fmaxf(v[0],v[1]), fmaxf(v[2],v[3]));
  #pragma unroll
  for(int o=16;o>0;o>>=1) mx = fmaxf(mx, __shfl_xor_sync(0xffffffffu, mx, o));
  if(lane==0) sred[warp]=mx;
  __syncthreads();
  float M = sred[0];
  #pragma unroll
  for(int w=1;w<8;w++) M = fmaxf(M, sred[w]);
  float s = 0.f;
  #pragma unroll
  for(int jj=0;jj<4;jj++){ v[jj] = ex2f_((v[jj]-M)*LOG2E); s += v[jj]; }
  #pragma unroll
  for(int o=16;o>0;o>>=1) s += __shfl_xor_sync(0xffffffffu, s, o);
  __syncthreads();
  if(lane==0) sred[warp]=s;
  __syncthreads();
  float tot = 0.f;
  #pragma unroll
  for(int w=0;w<8;w++) tot += sred[w];
  float inv = 1.f/tot;
  #pragma unroll
  for(int jj=0;jj<4;jj++) g_sp[b*1024 + t + jj*256] = v[jj]*inv;
}

// ============================================================================
// Kernel 4: flash attention, inter-CTA split-K (grid 256 = 128 Q-tiles x 2
// key-halves) + intra-CTA 2-group split + skip-rescale (max rarely changes).
// ============================================================================
#define KBLK 32
#define NIT  64
#define STAGE_E (2*KBLK*136)
#define FLASH_SMEM ((64*136 + 2*2*STAGE_E)*2)   // 87040 B
__global__ __launch_bounds__(256) void flash_kernel(){
  extern __shared__ __nv_bfloat16 smem[];
  __nv_bfloat16* sQ  = smem;
  __nv_bfloat16* sKV = smem + 64*136;
  int t=threadIdx.x, lane=t&31, warp=t>>5;
  int group = warp>>2, wl = warp&3, tg = t&127;
  int q    = blockIdx.x>>1, half = blockIdx.x&1;
  int q0   = q*64;
  int blk0 = half*128;
  int lr16 = lane&15, lh8 = (lane>>4)*8;
  __nv_bfloat16* gbase = sKV + group*(2*STAGE_E);

  auto issue = [&](int j32, int s){
    const char* gk = (const char*)(g_phi   + (size_t)j32*KBLK*C2);
    const char* gv = (const char*)(g_alpha + (size_t)j32*KBLK*C2);
    __nv_bfloat16* bK = gbase + s*STAGE_E;
    __nv_bfloat16* bV = bK + KBLK*136;
    for(int idx=tg; idx<KBLK*16; idx+=128){
      int r=idx>>4, c=idx&15;
      cp_async16(bK + r*136 + c*8, gk + idx*16);
      cp_async16(bV + r*136 + c*8, gv + idx*16);
    }
    CP_COMMIT();
  };

  issue(blk0+group,   0);
  issue(blk0+group+2, 1);

  const uint4* gq = (const uint4*)(g_theta + (size_t)q0*C2);
  for(int idx=t; idx<64*16; idx+=256){
    int r=idx>>4, c=idx&15;
    *(uint4*)(sQ + r*136 + c*8) = gq[idx];
  }
  __syncthreads();
  unsigned qf[8][4];
  #pragma unroll
  for(int kk=0;kk<8;kk++)
    ldmatrix_x4(qf[kk][0],qf[kk][1],qf[kk][2],qf[kk][3],
                smem_u32(sQ + (wl*16+lr16)*136 + kk*16 + lh8));

  float O[16][4];
  #pragma unroll
  for(int i=0;i<16;i++){O[i][0]=O[i][1]=O[i][2]=O[i][3]=0.f;}
  float mrow[2]={-1e30f,-1e30f}, lsum[2]={0.f,0.f};

  #pragma unroll 1
  for(int i=0;i<NIT;i++){
    if(i<NIT-1){ CP_WAIT(1); } else { CP_WAIT(0); }
    GBAR(1+group);
    __nv_bfloat16* sK = gbase + (i&1)*STAGE_E;
    __nv_bfloat16* sV = sK + KBLK*136;

    float S[4][4];
    #pragma unroll
    for(int ii=0;ii<4;ii++){S[ii][0]=S[ii][1]=S[ii][2]=S[ii][3]=0.f;}
    #pragma unroll
    for(int kk=0;kk<8;kk++){
      #pragma unroll
      for(int n2=0;n2<2;n2++){
        unsigned r0,r1,r2,r3;
        ldmatrix_x4(r0,r1,r2,r3, smem_u32(sK + (n2*16+lr16)*136 + kk*16 + lh8));
        mma_bf16(S[2*n2  ], qf[kk], r0, r2);
        mma_bf16(S[2*n2+1], qf[kk], r1, r3);
      }
    }
    // online softmax with skip-rescale: new max is rare (~ln(NIT) of NIT iters)
    #pragma unroll
    for(int h=0;h<2;h++){
      float mx = mrow[h];
      #pragma unroll
      for(int ii=0;ii<4;ii++) mx = fmaxf(mx, fmaxf(S[ii][2*h], S[ii][2*h+1]));
      mx = fmaxf(mx, __shfl_xor_sync(0xffffffffu, mx, 1));
      mx = fmaxf(mx, __shfl_xor_sync(0xffffffffu, mx, 2));
      float rs = 0.f;
      #pragma unroll
      for(int ii=0;ii<4;ii++){
        S[ii][2*h]   = ex2f_((S[ii][2*h]  -mx)*LOG2E);
        S[ii][2*h+1] = ex2f_((S[ii][2*h+1]-mx)*LOG2E);
        rs += S[ii][2*h] + S[ii][2*h+1];
      }
      rs += __shfl_xor_sync(0xffffffffu, rs, 1);
      rs += __shfl_xor_sync(0xffffffffu, rs, 2);
      if(mx > mrow[h]){
        float sc = ex2f_((mrow[h]-mx)*LOG2E);
        lsum[h] = lsum[h]*sc + rs;
        mrow[h] = mx;
        #pragma unroll
        for(int ii=0;ii<16;ii++){ O[ii][2*h]*=sc; O[ii][2*h+1]*=sc; }
      } else {
        lsum[h] += rs;
      }
    }
    #pragma unroll
    for(int kk=0;kk<2;kk++){
      unsigned pf[4];
      pf[0] = pack_bf2(S[2*kk  ][0], S[2*kk  ][1]);
      pf[1] = pack_bf2(S[2*kk  ][2], S[2*kk  ][3]);
      pf[2] = pack_bf2(S[2*kk+1][0], S[2*kk+1][1]);
      pf[3] = pack_bf2(S[2*kk+1][2], S[2*kk+1][3]);
      #pragma unroll
      for(int n2=0;n2<8;n2++){
        unsigned r0,r1,r2,r3;
        ldmatrix_x4_trans(r0,r1,r2,r3, smem_u32(sV + (kk*16+lr16)*136 + n2*16 + lh8));
        mma_bf16(O[2*n2  ], pf, r0, r1);
        mma_bf16(O[2*n2+1], pf, r2, r3);
      }
    }
    GBAR(1+group);
    if(i+2<NIT) issue(blk0 + 2*(i+2)+group, i&1);
  }

  // ---- merge the two intra-CTA groups, write unnormalized partials ----
  __syncthreads();
  float* s_O = (float*)sKV;
  float* s_m = s_O + 64*128;
  float* s_l = s_m + 64;
  int rrb = wl*16 + (lane>>2);
  if(group==1){
    #pragma unroll
    for(int h=0;h<2;h++){
      int rr = rrb + 8*h;
      s_m[rr] = mrow[h]; s_l[rr] = lsum[h];
      #pragma unroll
      for(int ii=0;ii<16;ii++){
        int col = ii*8 + (lane&3)*2;
        *(float2*)&s_O[rr*128 + col] = make_float2(O[ii][2*h], O[ii][2*h+1]);
      }
    }
  }
  __syncthreads();
  if(group==0){
    #pragma unroll
    for(int h=0;h<2;h++){
      int rr = rrb + 8*h;
      float ma = mrow[h], la = lsum[h];
      float mb = s_m[rr], lb = s_l[rr];
      float m = fmaxf(ma, mb);
      float sa = ex2f_((ma-m)*LOG2E), sb = ex2f_((mb-m)*LOG2E);
      int row = q0 + rr;
      if((lane&3)==0){ g_fm[half*N_TOK+row] = m; g_fl[half*N_TOK+row] = la*sa + lb*sb; }
      #pragma unroll
      for(int ii=0;ii<16;ii++){
        int col = ii*8 + (lane&3)*2;
        float2 ob = *(float2*)&s_O[rr*128 + col];
        *(float2*)(g_fO + ((size_t)half*N_TOK + row)*C2 + col) = make_float2(
            O[ii][2*h]*sa + ob.x*sb,
            O[ii][2*h+1]*sa + ob.y*sb);
      }
    }
  }
}

// ============================================================================
// Kernel 4b: merge the two key-halves -> normalized g_oattn.
// ============================================================================
__global__ __launch_bounds__(256) void flash_merge_kernel(){
  int t = threadIdx.x;
  int row = blockIdx.x*32 + (t>>3);
  int c0  = (t&7)*16;
  float m0 = g_fm[row],        l0 = g_fl[row];
  float m1 = g_fm[N_TOK+row],  l1 = g_fl[N_TOK+row];
  float m  = fmaxf(m0, m1);
  float s0 = ex2f_((m0-m)*LOG2E), s1 = ex2f_((m1-m)*LOG2E);
  float inv = 1.f/(l0*s0 + l1*s1);
  #pragma unroll
  for(int c=0;c<16;c+=4){
    float4 a = *(const float4*)&g_fO[(size_t)row*C2 + c0 + c];
    float4 b = *(const float4*)&g_fO[((size_t)N_TOK+row)*C2 + c0 + c];
    *(float4*)&g_oattn[(size_t)row*C2 + c0 + c] = make_float4(
        (a.x*s0 + b.x*s1)*inv, (a.y*s0 + b.y*s1)*inv,
        (a.z*s0 + b.z*s1)*inv, (a.w*s0 + b.w*s1)*inv);
  }
}

// ============================================================================
// Kernel 5: mod = oattn @ W_mask; out = mod * sp + x.
// ============================================================================
__global__ __launch_bounds__(256) void epilogue_kernel(
    const float* __restrict__ Wm, const float* __restrict__ x, float* __restrict__ out)
{
  __shared__ float As[32*132];
  __shared__ float Bs[16*260];
  int t = threadIdx.x;
  int m0 = blockIdx.x*32;
  for(int idx=t; idx<1024; idx+=256){
    int r=idx>>5, c4=idx&31;
    *(float4*)&As[r*132 + c4*4] = *(const float4*)&g_oattn[(size_t)(m0+r)*128 + c4*4];
  }
  float acc[8][4];
  #pragma unroll
  for(int i=0;i<8;i++){acc[i][0]=acc[i][1]=acc[i][2]=acc[i][3]=0.f;}
  int ty=t>>6, tx=t&63;
  for(int kc=0;kc<8;kc++){
    __syncthreads();
    for(int idx=t; idx<1024; idx+=256){
      int r=idx>>6, c4=idx&63;
      *(float4*)&Bs[r*260 + c4*4] = *(const float4*)&Wm[(size_t)(kc*16+r)*256 + c4*4];
    }
    __syncthreads();
    #pragma unroll
    for(int k=0;k<16;k++){
      float4 bv = *(float4*)&Bs[k*260 + tx*4];
      #pragma unroll
      for(int rr=0;rr<8;rr++){
        float a = As[(ty*8+rr)*132 + kc*16 + k];
        acc[rr][0] += a*bv.x; acc[rr][1] += a*bv.y;
        acc[rr][2] += a*bv.z; acc[rr][3] += a*bv.w;
      }
    }
  }
  #pragma unroll
  for(int rr=0;rr<8;rr++){
    int m = m0 + ty*8 + rr;
    float spv = g_sp[m];
    float4 xv = *(const float4*)&x[(size_t)m*256 + tx*4];
    *(float4*)&out[(size_t)m*256 + tx*4] = make_float4(
        acc[rr][0]*spv + xv.x, acc[rr][1]*spv + xv.y,
        acc[rr][2]*spv + xv.z, acc[rr][3]*spv + xv.w);
  }
}

// ============================================================================
extern "C" void kernel_launch(void* const* d_in, const int* in_sizes, int n_in,
                              void* d_out, int out_size)
{
  (void)in_sizes; (void)n_in; (void)out_size;
  const float* x  = (const float*)d_in[0];
  const float* Wt = (const float*)d_in[1];
  const float* bt = (const float*)d_in[2];
  const float* Wp = (const float*)d_in[3];
  const float* bp = (const float*)d_in[4];
  const float* Wa = (const float*)d_in[5];
  const float* ba = (const float*)d_in[6];
  const float* Wm = (const float*)d_in[7];
  const float* Wd = (const float*)d_in[8];
  const float* bd = (const float*)d_in[9];
  float* out = (float*)d_out;

  static cudaStream_t s2 = nullptr;
  static cudaEvent_t evF = nullptr, evJ = nullptr;
  if(!s2){
    cudaStreamCreateWithFlags(&s2, cudaStreamNonBlocking);
    cudaEventCreateWithFlags(&evF, cudaEventDisableTiming);
    cudaEventCreateWithFlags(&evJ, cudaEventDisableTiming);
    cudaFuncSetAttribute(proj_kernel,  cudaFuncAttributeMaxDynamicSharedMemorySize, PROJ_SMEM);
    cudaFuncSetAttribute(flash_kernel, cudaFuncAttributeMaxDynamicSharedMemorySize, FLASH_SMEM);
  }

  // launch order tuned so flash_kernel is launch #5 (ncu -s 5 -c 1 profiles it)
  convert_kernel<<<576, 256>>>(x, Wt, Wp, Wa);            // 0
  cudaEventRecord(evF, 0);
  cudaStreamWaitEvent(s2, evF, 0);
  dense_partial_kernel<<<DSLICES, 256, 0, s2>>>(x, Wd);   // 1
  reduce_kernel<<<256, 256, 0, s2>>>();                   // 2
  sp_softmax_kernel<<<8, 256, 0, s2>>>(bd);               // 3
  cudaEventRecord(evJ, s2);

  proj_kernel<<<dim3(128,1,3), 128, PROJ_SMEM>>>(bt, bp, ba);  // 4
  flash_kernel<<<256, 256, FLASH_SMEM>>>();                    // 5 <- profiled
  flash_merge_kernel<<<256, 256>>>();                          // 6

  cudaStreamWaitEvent(0, evJ, 0);
  epilogue_kernel<<<256, 256>>>(Wm, x, out);                   // 7
}

// round 13
// speedup vs baseline: 1.0194x; 1.0194x over previous
#include <cuda_runtime.h>
#include <cuda_bf16.h>

#define N_TOK 8192
#define C_IN  256
#define C2    128
#define HWX   1024
#define BATCH 8
#define KTOT  262144
#define DSLICES 256
#define DROWS   1024

// ---------------- scratch (device globals per harness rules) ----------------
__device__ __align__(16) __nv_bfloat16 g_xbf[N_TOK*C_IN];
__device__ __align__(16) __nv_bfloat16 g_Wbf[3*C_IN*C2];
__device__ __align__(16) __nv_bfloat16 g_theta[N_TOK*C2];
__device__ __align__(16) __nv_bfloat16 g_phi[N_TOK*C2];
__device__ __align__(16) __nv_bfloat16 g_alpha[N_TOK*C2];
__device__ __align__(16) float g_oattn[N_TOK*C2];
__device__ __align__(16) float g_partial[DSLICES*BATCH*HWX];
__device__ __align__(16) float g_logits[BATCH*HWX];
__device__ __align__(16) float g_sp[BATCH*HWX];
// flash split-K partials (2 halves)
__device__ __align__(16) float g_fO[2*N_TOK*C2];
__device__ __align__(16) float g_fm[2*N_TOK];
__device__ __align__(16) float g_fl[2*N_TOK];

// ---------------- helpers ----------------
__device__ __forceinline__ unsigned smem_u32(const void* p){
  return (unsigned)__cvta_generic_to_shared(p);
}
__device__ __forceinline__ void ldmatrix_x4(unsigned &r0, unsigned &r1, unsigned &r2, unsigned &r3, unsigned addr){
  asm volatile("ldmatrix.sync.aligned.m8n8.x4.shared.b16 {%0,%1,%2,%3}, [%4];"
    : "=r"(r0),"=r"(r1),"=r"(r2),"=r"(r3) : "r"(addr));
}
__device__ __forceinline__ void ldmatrix_x4_trans(unsigned &r0, unsigned &r1, unsigned &r2, unsigned &r3, unsigned addr){
  asm volatile("ldmatrix.sync.aligned.m8n8.x4.trans.shared.b16 {%0,%1,%2,%3}, [%4];"
    : "=r"(r0),"=r"(r1),"=r"(r2),"=r"(r3) : "r"(addr));
}
__device__ __forceinline__ void mma_bf16(float* d, const unsigned* a, unsigned b0, unsigned b1){
  asm volatile("mma.sync.aligned.m16n8k16.row.col.f32.bf16.bf16.f32 "
    "{%0,%1,%2,%3}, {%4,%5,%6,%7}, {%8,%9}, {%0,%1,%2,%3};"
    : "+f"(d[0]),"+f"(d[1]),"+f"(d[2]),"+f"(d[3])
    : "r"(a[0]),"r"(a[1]),"r"(a[2]),"r"(a[3]),"r"(b0),"r"(b1));
}
__device__ __forceinline__ float ex2f_(float x){ float y; asm("ex2.approx.ftz.f32 %0, %1;" : "=f"(y) : "f"(x)); return y; }
__device__ __forceinline__ unsigned pack_bf2(float lo, float hi){
  unsigned u; asm("cvt.rn.bf16x2.f32 %0, %1, %2;" : "=r"(u) : "f"(hi), "f"(lo)); return u;
}
__device__ __forceinline__ void cp_async16(void* sdst, const void* gsrc){
  asm volatile("cp.async.cg.shared.global [%0], [%1], 16;"
    :: "r"(smem_u32(sdst)), "l"(gsrc));
}
#define CP_COMMIT() asm volatile("cp.async.commit_group;" ::: "memory")
#define CP_WAIT(N)  asm volatile("cp.async.wait_group %0;" :: "n"(N) : "memory")
#define GBAR(id)    asm volatile("bar.sync %0, 128;" :: "r"(id) : "memory")
#define LOG2E 1.4426950408889634f

// ============================================================================
// Kernel 0: one-time bf16 conversion of x and the three projection weights.
// ============================================================================
__global__ __launch_bounds__(256) void convert_kernel(
    const float* __restrict__ x,
    const float* __restrict__ Wt, const float* __restrict__ Wp, const float* __restrict__ Wa)
{
  int t = threadIdx.x;
  if(blockIdx.x < 512){
    const float4* x4 = (const float4*)x;
    #pragma unroll
    for(int k=0;k<4;k++){
      size_t i = (size_t)blockIdx.x*1024 + k*256 + t;   // < 524288
      float4 v = x4[i];
      __nv_bfloat162 a = __float22bfloat162_rn(make_float2(v.x,v.y));
      __nv_bfloat162 b = __float22bfloat162_rn(make_float2(v.z,v.w));
      *(__nv_bfloat162*)(g_xbf + i*4    ) = a;
      *(__nv_bfloat162*)(g_xbf + i*4 + 2) = b;
    }
  } else {
    int idx = (blockIdx.x-512)*256 + t;                 // 0..16383
    for(; idx < 24576; idx += 64*256){
      int which = idx >> 13, off = idx & 8191;
      const float4* src = (const float4*)(which==0?Wt:(which==1?Wp:Wa));
      float4 v = src[off];
      __nv_bfloat162 a = __float22bfloat162_rn(make_float2(v.x,v.y));
      __nv_bfloat162 b = __float22bfloat162_rn(make_float2(v.z,v.w));
      __nv_bfloat16* dst = g_Wbf + which*C_IN*C2 + off*4;
      *(__nv_bfloat162*)(dst  ) = a;
      *(__nv_bfloat162*)(dst+2) = b;
    }
  }
}

// ============================================================================
// Kernel 1: projections theta/phi/alpha = x @ W + b  (bf16 mma, cp.async tiles)
// ============================================================================
#define PROJ_SMEM ((64*264 + 256*136)*2)
__global__ __launch_bounds__(128) void proj_kernel(
    const float* __restrict__ bt, const float* __restrict__ bp, const float* __restrict__ ba)
{
  extern __shared__ __nv_bfloat16 smem[];
  __nv_bfloat16* sA = smem;            // [64][264]
  __nv_bfloat16* sB = smem + 64*264;   // [256][136]
  const float* bias; __nv_bfloat16* outp;
  if      (blockIdx.z==0){bias=bt;outp=g_theta;}
  else if (blockIdx.z==1){bias=bp;outp=g_phi;}
  else                   {bias=ba;outp=g_alpha;}
  const __nv_bfloat16* W = g_Wbf + blockIdx.z*C_IN*C2;
  int t=threadIdx.x, lane=t&31, warp=t>>5;
  int m0 = blockIdx.x*64;

  for(int idx=t; idx<2048; idx+=128){
    int r=idx>>5, c=idx&31;
    cp_async16(sA + r*264 + c*8, g_xbf + (size_t)(m0+r)*C_IN + c*8);
  }
  for(int idx=t; idx<4096; idx+=128){
    int r=idx>>4, c=idx&15;
    cp_async16(sB + r*136 + c*8, W + r*C2 + c*8);
  }
  CP_COMMIT(); CP_WAIT(0);
  __syncthreads();

  float acc[16][4];
  #pragma unroll
  for(int i=0;i<16;i++){acc[i][0]=acc[i][1]=acc[i][2]=acc[i][3]=0.f;}
  int lr16 = lane&15, lh8 = (lane>>4)*8;

  #pragma unroll
  for(int kk=0;kk<16;kk++){
    unsigned af[4];
    ldmatrix_x4(af[0],af[1],af[2],af[3], smem_u32(sA + (warp*16+lr16)*264 + kk*16 + lh8));
    #pragma unroll
    for(int n2=0;n2<8;n2++){
      unsigned r0,r1,r2,r3;
      ldmatrix_x4_trans(r0,r1,r2,r3, smem_u32(sB + (kk*16+lr16)*136 + n2*16 + lh8));
      mma_bf16(acc[2*n2  ], af, r0, r1);
      mma_bf16(acc[2*n2+1], af, r2, r3);
    }
  }
  int row = m0 + warp*16 + (lane>>2);
  #pragma unroll
  for(int nt=0;nt<16;nt++){
    int col = nt*8 + (lane&3)*2;
    float b0v = bias[col], b1v = bias[col+1];
    *(__nv_bfloat162*)(outp + (size_t)row*C2 + col)
        = __float22bfloat162_rn(make_float2(acc[nt][0]+b0v, acc[nt][1]+b1v));
    *(__nv_bfloat162*)(outp + (size_t)(row+8)*C2 + col)
        = __float22bfloat162_rn(make_float2(acc[nt][2]+b0v, acc[nt][3]+b1v));
  }
}

// ============================================================================
// Kernel 2: dense gate split-K partials (proven config: grid 256 x 1024 rows)
// ============================================================================
__global__ __launch_bounds__(256) void dense_partial_kernel(
    const float* __restrict__ x, const float* __restrict__ Wd)
{
  __shared__ float xs[8*DROWS];
  int t = threadIdx.x;
  int i0 = blockIdx.x*DROWS;
  for(int idx=t; idx<2048; idx+=256){
    int b=idx>>8, c4=idx&255;
    *(float4*)&xs[b*DROWS + c4*4] = *(const float4*)&x[(size_t)b*KTOT + i0 + c4*4];
  }
  __syncthreads();
  unsigned long long acc0[8], acc1[8];
  #pragma unroll
  for(int b=0;b<8;b++){acc0[b]=0ull; acc1[b]=0ull;}
  const float4* W4 = (const float4*)Wd + (size_t)i0*256 + t;
  #pragma unroll 8
  for(int i=0;i<DROWS;i++){
    float4 w = __ldcs(&W4[(size_t)i*256]);
    unsigned long long w01, w23;
    asm("mov.b64 %0, {%1,%2};" : "=l"(w01) : "f"(w.x), "f"(w.y));
    asm("mov.b64 %0, {%1,%2};" : "=l"(w23) : "f"(w.z), "f"(w.w));
    #pragma unroll
    for(int b=0;b<8;b++){
      float xv = xs[b*DROWS+i];
      unsigned long long xx;
      asm("mov.b64 %0, {%1,%1};" : "=l"(xx) : "f"(xv));
      asm("fma.rn.f32x2 %0, %1, %2, %0;" : "+l"(acc0[b]) : "l"(w01), "l"(xx));
      asm("fma.rn.f32x2 %0, %1, %2, %0;" : "+l"(acc1[b]) : "l"(w23), "l"(xx));
    }
  }
  float* out = g_partial + (size_t)blockIdx.x*8192;
  #pragma unroll
  for(int b=0;b<8;b++){
    float lo0,hi0,lo1,hi1;
    asm("mov.b64 {%0,%1}, %2;" : "=f"(lo0),"=f"(hi0) : "l"(acc0[b]));
    asm("mov.b64 {%0,%1}, %2;" : "=f"(lo1),"=f"(hi1) : "l"(acc1[b]));
    *(float4*)&out[b*1024 + t*4] = make_float4(lo0,hi0,lo1,hi1);
  }
}

// ============================================================================
// Kernel 3a: reduce DSLICES partial slices -> g_logits[8192].
// ============================================================================
__global__ __launch_bounds__(256) void reduce_kernel(){
  __shared__ float red[256];
  int t = threadIdx.x;
  int c = t & 31, r = t >> 5;
  int col = blockIdx.x*32 + c;
  float s = 0.f;
  #pragma unroll 8
  for(int sl=r; sl<DSLICES; sl+=8) s += g_partial[(size_t)sl*8192 + col];
  red[t] = s;
  __syncthreads();
  if(t<128) red[t] += red[t+128];
  __syncthreads();
  if(t<64)  red[t] += red[t+64];
  __syncthreads();
  if(t<32)  g_logits[blockIdx.x*32 + t] = red[t] + red[t+32];
}

// ============================================================================
// Kernel 3b: softmax over 1024 positions per batch.
// ============================================================================
__global__ __launch_bounds__(256) void sp_softmax_kernel(const float* __restrict__ bd){
  int b = blockIdx.x, t = threadIdx.x, lane = t&31, warp = t>>5;
  __shared__ float sred[8];
  float v[4];
  #pragma unroll
  for(int jj=0;jj<4;jj++) v[jj] = g_logits[b*1024 + t + jj*256] + bd[t + jj*256];
  float mx = fmaxf(fmaxf(v[0],v[1]), fmaxf(v[2],v[3]));
  #pragma unroll
  for(int o=16;o>0;o>>=1) mx = fmaxf(mx, __shfl_xor_sync(0xffffffffu, mx, o));
  if(lane==0) sred[warp]=mx;
  __syncthreads();
  float M = sred[0];
  #pragma unroll
  for(int w=1;w<8;w++) M = fmaxf(M, sred[w]);
  float s = 0.f;
  #pragma unroll
  for(int jj=0;jj<4;jj++){ v[jj] = ex2f_((v[jj]-M)*LOG2E); s += v[jj]; }
  #pragma unroll
  for(int o=16;o>0;o>>=1) s += __shfl_xor_sync(0xffffffffu, s, o);
  __syncthreads();
  if(lane==0) sred[warp]=s;
  __syncthreads();
  float tot = 0.f;
  #pragma unroll
  for(int w=0;w<8;w++) tot += sred[w];
  float inv = 1.f/tot;
  #pragma unroll
  for(int jj=0;jj<4;jj++) g_sp[b*1024 + t + jj*256] = v[jj]*inv;
}

// ============================================================================
// Kernel 4: flash attention, inter-CTA split-K (grid 256 = 128 Q-tiles x 2
// key-halves) + intra-CTA 2-group split. __launch_bounds__(256,2) forces
// regs<=128 so 2 CTAs/SM actually co-reside (87KB smem allows it).
// ============================================================================
#define KBLK 32
#define NIT  64
#define STAGE_E (2*KBLK*136)
#define FLASH_SMEM ((64*136 + 2*2*STAGE_E)*2)   // 87040 B
__global__ __launch_bounds__(256, 2) void flash_kernel(){
  extern __shared__ __nv_bfloat16 smem[];
  __nv_bfloat16* sQ  = smem;
  __nv_bfloat16* sKV = smem + 64*136;
  int t=threadIdx.x, lane=t&31, warp=t>>5;
  int group = warp>>2, wl = warp&3, tg = t&127;
  int q    = blockIdx.x>>1, half = blockIdx.x&1;
  int q0   = q*64;
  int blk0 = half*128;
  int lr16 = lane&15, lh8 = (lane>>4)*8;
  __nv_bfloat16* gbase = sKV + group*(2*STAGE_E);

  auto issue = [&](int j32, int s){
    const char* gk = (const char*)(g_phi   + (size_t)j32*KBLK*C2);
    const char* gv = (const char*)(g_alpha + (size_t)j32*KBLK*C2);
    __nv_bfloat16* bK = gbase + s*STAGE_E;
    __nv_bfloat16* bV = bK + KBLK*136;
    for(int idx=tg; idx<KBLK*16; idx+=128){
      int r=idx>>4, c=idx&15;
      cp_async16(bK + r*136 + c*8, gk + idx*16);
      cp_async16(bV + r*136 + c*8, gv + idx*16);
    }
    CP_COMMIT();
  };

  issue(blk0+group,   0);
  issue(blk0+group+2, 1);

  const uint4* gq = (const uint4*)(g_theta + (size_t)q0*C2);
  for(int idx=t; idx<64*16; idx+=256){
    int r=idx>>4, c=idx&15;
    *(uint4*)(sQ + r*136 + c*8) = gq[idx];
  }
  __syncthreads();
  unsigned qf[8][4];
  #pragma unroll
  for(int kk=0;kk<8;kk++)
    ldmatrix_x4(qf[kk][0],qf[kk][1],qf[kk][2],qf[kk][3],
                smem_u32(sQ + (wl*16+lr16)*136 + kk*16 + lh8));

  float O[16][4];
  #pragma unroll
  for(int i=0;i<16;i++){O[i][0]=O[i][1]=O[i][2]=O[i][3]=0.f;}
  float mrow[2]={-1e30f,-1e30f}, lsum[2]={0.f,0.f};

  #pragma unroll 1
  for(int i=0;i<NIT;i++){
    if(i<NIT-1){ CP_WAIT(1); } else { CP_WAIT(0); }
    GBAR(1+group);
    __nv_bfloat16* sK = gbase + (i&1)*STAGE_E;
    __nv_bfloat16* sV = sK + KBLK*136;

    float S[4][4];
    #pragma unroll
    for(int ii=0;ii<4;ii++){S[ii][0]=S[ii][1]=S[ii][2]=S[ii][3]=0.f;}
    #pragma unroll
    for(int kk=0;kk<8;kk++){
      #pragma unroll
      for(int n2=0;n2<2;n2++){
        unsigned r0,r1,r2,r3;
        ldmatrix_x4(r0,r1,r2,r3, smem_u32(sK + (n2*16+lr16)*136 + kk*16 + lh8));
        mma_bf16(S[2*n2  ], qf[kk], r0, r2);
        mma_bf16(S[2*n2+1], qf[kk], r1, r3);
      }
    }
    // online softmax with skip-rescale
    #pragma unroll
    for(int h=0;h<2;h++){
      float mx = mrow[h];
      #pragma unroll
      for(int ii=0;ii<4;ii++) mx = fmaxf(mx, fmaxf(S[ii][2*h], S[ii][2*h+1]));
      mx = fmaxf(mx, __shfl_xor_sync(0xffffffffu, mx, 1));
      mx = fmaxf(mx, __shfl_xor_sync(0xffffffffu, mx, 2));
      float rs = 0.f;
      #pragma unroll
      for(int ii=0;ii<4;ii++){
        S[ii][2*h]   = ex2f_((S[ii][2*h]  -mx)*LOG2E);
        S[ii][2*h+1] = ex2f_((S[ii][2*h+1]-mx)*LOG2E);
        rs += S[ii][2*h] + S[ii][2*h+1];
      }
      rs += __shfl_xor_sync(0xffffffffu, rs, 1);
      rs += __shfl_xor_sync(0xffffffffu, rs, 2);
      if(mx > mrow[h]){
        float sc = ex2f_((mrow[h]-mx)*LOG2E);
        lsum[h] = lsum[h]*sc + rs;
        mrow[h] = mx;
        #pragma unroll
        for(int ii=0;ii<16;ii++){ O[ii][2*h]*=sc; O[ii][2*h+1]*=sc; }
      } else {
        lsum[h] += rs;
      }
    }
    #pragma unroll
    for(int kk=0;kk<2;kk++){
      unsigned pf[4];
      pf[0] = pack_bf2(S[2*kk  ][0], S[2*kk  ][1]);
      pf[1] = pack_bf2(S[2*kk  ][2], S[2*kk  ][3]);
      pf[2] = pack_bf2(S[2*kk+1][0], S[2*kk+1][1]);
      pf[3] = pack_bf2(S[2*kk+1][2], S[2*kk+1][3]);
      #pragma unroll
      for(int n2=0;n2<8;n2++){
        unsigned r0,r1,r2,r3;
        ldmatrix_x4_trans(r0,r1,r2,r3, smem_u32(sV + (kk*16+lr16)*136 + n2*16 + lh8));
        mma_bf16(O[2*n2  ], pf, r0, r1);
        mma_bf16(O[2*n2+1], pf, r2, r3);
      }
    }
    GBAR(1+group);
    if(i+2<NIT) issue(blk0 + 2*(i+2)+group, i&1);
  }

  // ---- merge the two intra-CTA groups, write unnormalized partials ----
  __syncthreads();
  float* s_O = (float*)sKV;
  float* s_m = s_O + 64*128;
  float* s_l = s_m + 64;
  int rrb = wl*16 + (lane>>2);
  if(group==1){
    #pragma unroll
    for(int h=0;h<2;h++){
      int rr = rrb + 8*h;
      s_m[rr] = mrow[h]; s_l[rr] = lsum[h];
      #pragma unroll
      for(int ii=0;ii<16;ii++){
        int col = ii*8 + (lane&3)*2;
        *(float2*)&s_O[rr*128 + col] = make_float2(O[ii][2*h], O[ii][2*h+1]);
      }
    }
  }
  __syncthreads();
  if(group==0){
    #pragma unroll
    for(int h=0;h<2;h++){
      int rr = rrb + 8*h;
      float ma = mrow[h], la = lsum[h];
      float mb = s_m[rr], lb = s_l[rr];
      float m = fmaxf(ma, mb);
      float sa = ex2f_((ma-m)*LOG2E), sb = ex2f_((mb-m)*LOG2E);
      int row = q0 + rr;
      if((lane&3)==0){ g_fm[half*N_TOK+row] = m; g_fl[half*N_TOK+row] = la*sa + lb*sb; }
      #pragma unroll
      for(int ii=0;ii<16;ii++){
        int col = ii*8 + (lane&3)*2;
        float2 ob = *(float2*)&s_O[rr*128 + col];
        *(float2*)(g_fO + ((size_t)half*N_TOK + row)*C2 + col) = make_float2(
            O[ii][2*h]*sa + ob.x*sb,
            O[ii][2*h+1]*sa + ob.y*sb);
      }
    }
  }
}

// ============================================================================
// Kernel 4b: merge the two key-halves -> normalized g_oattn.
// ============================================================================
__global__ __launch_bounds__(256) void flash_merge_kernel(){
  int t = threadIdx.x;
  int row = blockIdx.x*32 + (t>>3);
  int c0  = (t&7)*16;
  float m0 = g_fm[row],        l0 = g_fl[row];
  float m1 = g_fm[N_TOK+row],  l1 = g_fl[N_TOK+row];
  float m  = fmaxf(m0, m1);
  float s0 = ex2f_((m0-m)*LOG2E), s1 = ex2f_((m1-m)*LOG2E);
  float inv = 1.f/(l0*s0 + l1*s1);
  #pragma unroll
  for(int c=0;c<16;c+=4){
    float4 a = *(const float4*)&g_fO[(size_t)row*C2 + c0 + c];
    float4 b = *(const float4*)&g_fO[((size_t)N_TOK+row)*C2 + c0 + c];
    *(float4*)&g_oattn[(size_t)row*C2 + c0 + c] = make_float4(
        (a.x*s0 + b.x*s1)*inv, (a.y*s0 + b.y*s1)*inv,
        (a.z*s0 + b.z*s1)*inv, (a.w*s0 + b.w*s1)*inv);
  }
}

// ============================================================================
// Kernel 5: mod = oattn @ W_mask; out = mod * sp + x.
// ============================================================================
__global__ __launch_bounds__(256) void epilogue_kernel(
    const float* __restrict__ Wm, const float* __restrict__ x, float* __restrict__ out)
{
  __shared__ float As[32*132];
  __shared__ float Bs[16*260];
  int t = threadIdx.x;
  int m0 = blockIdx.x*32;
  for(int idx=t; idx<1024; idx+=256){
    int r=idx>>5, c4=idx&31;
    *(float4*)&As[r*132 + c4*4] = *(const float4*)&g_oattn[(size_t)(m0+r)*128 + c4*4];
  }
  float acc[8][4];
  #pragma unroll
  for(int i=0;i<8;i++){acc[i][0]=acc[i][1]=acc[i][2]=acc[i][3]=0.f;}
  int ty=t>>6, tx=t&63;
  for(int kc=0;kc<8;kc++){
    __syncthreads();
    for(int idx=t; idx<1024; idx+=256){
      int r=idx>>6, c4=idx&63;
      *(float4*)&Bs[r*260 + c4*4] = *(const float4*)&Wm[(size_t)(kc*16+r)*256 + c4*4];
    }
    __syncthreads();
    #pragma unroll
    for(int k=0;k<16;k++){
      float4 bv = *(float4*)&Bs[k*260 + tx*4];
      #pragma unroll
      for(int rr=0;rr<8;rr++){
        float a = As[(ty*8+rr)*132 + kc*16 + k];
        acc[rr][0] += a*bv.x; acc[rr][1] += a*bv.y;
        acc[rr][2] += a*bv.z; acc[rr][3] += a*bv.w;
      }
    }
  }
  #pragma unroll
  for(int rr=0;rr<8;rr++){
    int m = m0 + ty*8 + rr;
    float spv = g_sp[m];
    float4 xv = *(const float4*)&x[(size_t)m*256 + tx*4];
    *(float4*)&out[(size_t)m*256 + tx*4] = make_float4(
        acc[rr][0]*spv + xv.x, acc[rr][1]*spv + xv.y,
        acc[rr][2]*spv + xv.z, acc[rr][3]*spv + xv.w);
  }
}

// ============================================================================
extern "C" void kernel_launch(void* const* d_in, const int* in_sizes, int n_in,
                              void* d_out, int out_size)
{
  (void)in_sizes; (void)n_in; (void)out_size;
  const float* x  = (const float*)d_in[0];
  const float* Wt = (const float*)d_in[1];
  const float* bt = (const float*)d_in[2];
  const float* Wp = (const float*)d_in[3];
  const float* bp = (const float*)d_in[4];
  const float* Wa = (const float*)d_in[5];
  const float* ba = (const float*)d_in[6];
  const float* Wm = (const float*)d_in[7];
  const float* Wd = (const float*)d_in[8];
  const float* bd = (const float*)d_in[9];
  float* out = (float*)d_out;

  static cudaStream_t s2 = nullptr;
  static cudaEvent_t evF = nullptr, evJ = nullptr;
  if(!s2){
    cudaStreamCreateWithFlags(&s2, cudaStreamNonBlocking);
    cudaEventCreateWithFlags(&evF, cudaEventDisableTiming);
    cudaEventCreateWithFlags(&evJ, cudaEventDisableTiming);
    cudaFuncSetAttribute(proj_kernel,  cudaFuncAttributeMaxDynamicSharedMemorySize, PROJ_SMEM);
    cudaFuncSetAttribute(flash_kernel, cudaFuncAttributeMaxDynamicSharedMemorySize, FLASH_SMEM);
  }

  // fork for side stream (dense chain starts immediately at replay)
  cudaEventRecord(evF, 0);
  cudaStreamWaitEvent(s2, evF, 0);

  // enqueue order chosen so flash is the 4th kernel (ncu -s 5 -c 1 captures #4)
  convert_kernel<<<576, 256>>>(x, Wt, Wp, Wa);                 // 1
  proj_kernel<<<dim3(128,1,3), 128, PROJ_SMEM>>>(bt, bp, ba);  // 2
  dense_partial_kernel<<<DSLICES, 256, 0, s2>>>(x, Wd);        // 3 (s2)
  flash_kernel<<<256, 256, FLASH_SMEM>>>();                    // 4 <- profiled
  flash_merge_kernel<<<256, 256>>>();                          // 5
  reduce_kernel<<<256, 256, 0, s2>>>();                        // 6 (s2)
  sp_softmax_kernel<<<8, 256, 0, s2>>>(bd);                    // 7 (s2)
  cudaEventRecord(evJ, s2);

  cudaStreamWaitEvent(0, evJ, 0);
  epilogue_kernel<<<256, 256>>>(Wm, x, out);                   // 8
}